// round 8
// baseline (speedup 1.0000x reference)
#include <cuda_runtime.h>
#include <cuda_fp16.h>
#include <math.h>
#include <stdint.h>

// ---------------------------------------------------------------------------
// Problem constants
// ---------------------------------------------------------------------------
#define BN   2
#define CH   128
#define HH   128
#define WW   128
#define TOT  (BN*CH*HH*WW)          // 4194304
#define NSEQ (BN*CH*HH)             // 32768 sequences
#define D_INNER 32
#define D_STATE 16
#define GCN  16
#define LSEQ 8
#define GROUPS 4
#define GRP_CNT ((CH/GROUPS)*HH*WW) // 524288 per (b, group)

// ---------------------------------------------------------------------------
// Scratch (static device memory; no allocation allowed)
// ---------------------------------------------------------------------------
__device__ float g_y[TOT];       // conv2d output
__device__ float g_m[TOT];       // mamba output (pre-GroupNorm)
__device__ float g_stats[16];    // (b,group) -> {sum, sumsq}
// weight tiles: [tap 0..8], each 128ci x 128co fp16, swizzled, 32KB
__device__ __align__(16) unsigned char g_wt[9 * 32768];

// smem layout for conv kernel (dynamic):
//  [0,      34816)  A tile: 136 rows(wp) x 128 ci fp16, 256B rows, swizzled
//  [34816, 100352)  2 weight buffers x 32768 (double buffer)
//  bounce (epilogue) reuses [0, 67584): 128 w x 132 co f32
#define AH_OFF 0
#define W_OFF  34816
#define CSMEM  (W_OFF + 2*32768)   // 100352

// swizzle: off = row*256 + col2B; phys = off ^ ((row&7)<<4)
__host__ __device__ __forceinline__ uint32_t swz(uint32_t row, uint32_t colByte) {
    uint32_t off = row * 256u + colByte;
    return off ^ ((row & 7u) << 4);
}

__device__ __forceinline__ uint32_t smem_u32(const void* p) {
    uint32_t a;
    asm("{ .reg .u64 t; cvta.to.shared.u64 t, %1; cvt.u32.u64 %0, t; }" : "=r"(a) : "l"(p));
    return a;
}

#define LDSM_X4(r0,r1,r2,r3,addr) \
    asm volatile("ldmatrix.sync.aligned.m8n8.x4.shared.b16 {%0,%1,%2,%3}, [%4];" \
        : "=r"(r0), "=r"(r1), "=r"(r2), "=r"(r3) : "r"(addr))
#define LDSM_X4_T(r0,r1,r2,r3,addr) \
    asm volatile("ldmatrix.sync.aligned.m8n8.x4.trans.shared.b16 {%0,%1,%2,%3}, [%4];" \
        : "=r"(r0), "=r"(r1), "=r"(r2), "=r"(r3) : "r"(addr))
#define MMA16816(c0,c1,c2,c3,a0,a1,a2,a3,b0,b1) \
    asm volatile("mma.sync.aligned.m16n8k16.row.col.f32.f16.f16.f32 " \
        "{%0,%1,%2,%3}, {%4,%5,%6,%7}, {%8,%9}, {%0,%1,%2,%3};" \
        : "+f"(c0), "+f"(c1), "+f"(c2), "+f"(c3) \
        : "r"(a0), "r"(a1), "r"(a2), "r"(a3), "r"(b0), "r"(b1))
#define CP_ASYNC16(dst, src) \
    asm volatile("cp.async.cg.shared.global [%0], [%1], 16;" :: "r"(dst), "l"(src))
#define CP_COMMIT() asm volatile("cp.async.commit_group;")

// ---------------------------------------------------------------------------
// Prep: conv weights -> fp16 swizzled [ci][co] tiles; zero stats
// ---------------------------------------------------------------------------
__global__ void prep_kernel(const float* __restrict__ cw) {
    int idx = blockIdx.x * 256 + threadIdx.x;
    if (blockIdx.x == 0 && threadIdx.x < 16) g_stats[threadIdx.x] = 0.f;
    if (idx >= 9 * 128 * 128) return;
    int tap = idx >> 14;
    int rem = idx & 16383;
    int ci = rem >> 7, co = rem & 127;
    float v = cw[co * 1152 + ci * 9 + tap];
    uint32_t o = swz((uint32_t)ci, (uint32_t)co * 2u);
    *(__half*)(g_wt + (size_t)tap * 32768 + o) = __float2half(v);
}

// ---------------------------------------------------------------------------
// Conv 3x3 via mma.sync fp16 single pass. One block = one (b,h).
// D[w][co] single accumulator; tap w-shift = A row offset at ldmatrix.
// ---------------------------------------------------------------------------
__global__ __launch_bounds__(256, 2) void conv_mma_kernel(
    const float* __restrict__ x, const float* __restrict__ bias)
{
    extern __shared__ __align__(1024) char smem[];
    const uint32_t sb = smem_u32(smem);
    const int tid = threadIdx.x, warp = tid >> 5, lane = tid & 31;
    const int h = blockIdx.x, b = blockIdx.y;
    const int m0 = warp * 16;           // w-row base for this warp

    float acc[64];
#pragma unroll
    for (int i = 0; i < 64; i++) acc[i] = 0.f;

    // prologue: prefetch weight tile 0 into slot 0
    {
        const char* src = (const char*)g_wt + tid * 16;
        uint32_t dst = sb + W_OFF + tid * 16;
#pragma unroll
        for (int i = 0; i < 8; i++) CP_ASYNC16(dst + i * 4096, src + i * 4096);
        CP_COMMIT();
    }
    int issued = 1;

#pragma unroll 1
    for (int dh = 0; dh < 3; dh++) {
        __syncthreads();   // everyone done reading previous A
        // ---- build A tile (fp16) for input row hr ----
        {
            const int hr = h + dh - 1;
            const bool valid = (hr >= 0) && (hr < HH);
            // zero halo rows 0 and 129
            {
                uint32_t rz = (tid & 128) ? 129u : 0u;
                uint32_t ciz = (uint32_t)(tid & 127);
                *(__half*)(smem + AH_OFF + swz(rz, ciz * 2u)) = __float2half(0.f);
            }
#pragma unroll 1
            for (int k = 0; k < 16; k++) {
                const int ci = warp + 8 * k;
                float4 q = make_float4(0.f, 0.f, 0.f, 0.f);
                if (valid)
                    q = *(const float4*)&x[((b * CH + ci) * HH + hr) * WW + lane * 4];
                float vv[4] = {q.x, q.y, q.z, q.w};
#pragma unroll
                for (int e = 0; e < 4; e++) {
                    uint32_t wp = (uint32_t)(lane * 4 + e + 1);
                    *(__half*)(smem + AH_OFF + swz(wp, (uint32_t)ci * 2u)) =
                        __float2half(vv[e]);
                }
            }
        }

#pragma unroll 1
        for (int dw = 0; dw < 3; dw++) {
            const int L = dh * 3 + dw;
            // tile L in flight (or done); drain, then barrier makes it visible
            asm volatile("cp.async.wait_group 0;");
            __syncthreads();
            // prefetch tile L+1 into the other slot (free: stage L-1 done)
            if (issued < 9) {
                const char* src = (const char*)g_wt + (size_t)issued * 32768 + tid * 16;
                uint32_t dst = sb + W_OFF + (uint32_t)(issued & 1) * 32768 + tid * 16;
#pragma unroll
                for (int i = 0; i < 8; i++) CP_ASYNC16(dst + i * 4096, src + i * 4096);
                CP_COMMIT();
                issued++;
            }
            const uint32_t wB = sb + W_OFF + (uint32_t)(L & 1) * 32768;
            // A ldmatrix lane geometry
            const uint32_t arow = (uint32_t)(m0 + dw + ((lane >> 3) & 1) * 8 + (lane & 7));
            const uint32_t arbase = sb + AH_OFF + arow * 256u;
            const uint32_t axor = (arow & 7u) << 4;
            const uint32_t brow = (uint32_t)(lane & 15);
            const uint32_t bg = (uint32_t)(lane >> 4);
#pragma unroll
            for (int ks = 0; ks < 8; ks++) {
                uint32_t a0, a1, a2, a3;
                uint32_t aaddr = arbase + ((((uint32_t)(ks * 2) + bg) << 4) ^ axor);
                LDSM_X4(a0, a1, a2, a3, aaddr);
                const uint32_t br = (uint32_t)(ks * 16) + brow;
                const uint32_t brbase = wB + br * 256u;
                const uint32_t bxor = (br & 7u) << 4;
#pragma unroll
                for (int j2 = 0; j2 < 8; j2++) {
                    uint32_t b0, b1, b2, b3;
                    uint32_t baddr = brbase + ((((uint32_t)(j2 * 2) + bg) << 4) ^ bxor);
                    LDSM_X4_T(b0, b1, b2, b3, baddr);
                    MMA16816(acc[j2 * 8 + 0], acc[j2 * 8 + 1], acc[j2 * 8 + 2], acc[j2 * 8 + 3],
                             a0, a1, a2, a3, b0, b1);
                    MMA16816(acc[j2 * 8 + 4], acc[j2 * 8 + 5], acc[j2 * 8 + 6], acc[j2 * 8 + 7],
                             a0, a1, a2, a3, b2, b3);
                }
            }
        }
    }

    // ---- epilogue: regs -> bounce[w][co] (+bias) -> transposed global ----
    __syncthreads();
    {
        float* bounce = (float*)smem;          // [128][132]
        const int q = lane >> 2, p = lane & 3;
        const int r0 = m0 + q, r1 = m0 + q + 8;
#pragma unroll
        for (int j = 0; j < 16; j++) {
            const int co = j * 8 + p * 2;
            float2 bv = *(const float2*)&bias[co];
            *(float2*)&bounce[r0 * 132 + co] =
                make_float2(acc[j * 4 + 0] + bv.x, acc[j * 4 + 1] + bv.y);
            *(float2*)&bounce[r1 * 132 + co] =
                make_float2(acc[j * 4 + 2] + bv.x, acc[j * 4 + 3] + bv.y);
        }
        __syncthreads();
        const int co2 = tid >> 1, seg = (tid & 1) * 64;
        float* dst = &g_y[((b * CH + co2) * HH + h) * WW + seg];
#pragma unroll
        for (int j = 0; j < 64; j += 4) {
            *(float4*)&dst[j] = make_float4(
                bounce[(seg + j + 0) * 132 + co2], bounce[(seg + j + 1) * 132 + co2],
                bounce[(seg + j + 2) * 132 + co2], bounce[(seg + j + 3) * 132 + co2]);
        }
    }
}

// ---------------------------------------------------------------------------
// Mamba kernel: one warp per sequence, lane = d_inner channel.
// s_xc stride 33 (conflict-free dtin gather). dtin computed distributed.
// ---------------------------------------------------------------------------
__global__ __launch_bounds__(256) void mamba_kernel(
    const float* __restrict__ in_proj_w, const float* __restrict__ c1w,
    const float* __restrict__ c1b, const float* __restrict__ xpw,
    const float* __restrict__ dtw, const float* __restrict__ dtb,
    const float* __restrict__ A_log, const float* __restrict__ Dp,
    const float* __restrict__ opw)
{
    __shared__ float s_ipw[16 * 64];
    __shared__ float s_xpwt[32 * 33];
    __shared__ float s_At[16 * 32];
    __shared__ float s_opwt[32 * 16];
    __shared__ float s_c1w[32 * 4];
    __shared__ float s_c1b[32], s_dtw[32], s_dtb[32], s_D[32];
    __shared__ float s_seq[8][128];
    __shared__ float s_xc[8][LSEQ * 33];   // stride 33
    __shared__ float s_bc[8][LSEQ * 32];
    __shared__ float sm_s1, sm_s2;

    const int tid = threadIdx.x;

    for (int idx = tid; idx < 16 * 64; idx += 256) {
        int k = idx >> 6, e = idx & 63;
        s_ipw[idx] = in_proj_w[e * 16 + k];
    }
    for (int idx = tid; idx < 32 * 33; idx += 256) {
        int d = idx / 33, e = idx - d * 33;
        s_xpwt[idx] = xpw[e * 32 + d];
    }
    for (int idx = tid; idx < 16 * 32; idx += 256) {
        int s = idx >> 5, d = idx & 31;
        s_At[idx] = -__expf(A_log[d * 16 + s]);
    }
    for (int idx = tid; idx < 32 * 16; idx += 256) {
        int d = idx >> 4, g = idx & 15;
        s_opwt[idx] = opw[g * 32 + d];
    }
    if (tid < 128) s_c1w[tid] = c1w[tid];
    if (tid < 32) {
        s_c1b[tid] = c1b[tid];
        s_dtw[tid] = dtw[tid];
        s_dtb[tid] = dtb[tid];
        s_D[tid]   = Dp[tid];
    }
    if (tid == 0) { sm_s1 = 0.f; sm_s2 = 0.f; }
    __syncthreads();

    const int warp = tid >> 5;
    const int lane = tid & 31;
    const int n = blockIdx.x * 8 + warp;
    const int c = (n >> 7) & 127;
    const int b = n >> 14;

    const float* yrow = g_y + (size_t)n * 128;
    float* seq = s_seq[warp];
#pragma unroll
    for (int i = 0; i < 4; i++) seq[i * 32 + lane] = yrow[i * 32 + lane];
    __syncwarp();

    float xi[LSEQ], zv[LSEQ];
#pragma unroll
    for (int l = 0; l < LSEQ; l++) {
        float sx = 0.f, sz = 0.f;
#pragma unroll
        for (int k = 0; k < GCN; k++) {
            float sv = seq[l * GCN + k];
            sx = fmaf(sv, s_ipw[k * 64 + lane], sx);
            sz = fmaf(sv, s_ipw[k * 64 + 32 + lane], sz);
        }
        xi[l] = sx; zv[l] = sz;
    }

    float cw0 = s_c1w[lane * 4 + 0], cw1 = s_c1w[lane * 4 + 1];
    float cw2 = s_c1w[lane * 4 + 2], cw3 = s_c1w[lane * 4 + 3];
    float cb = s_c1b[lane];
    float xc[LSEQ];
#pragma unroll
    for (int l = 0; l < LSEQ; l++) {
        float a = fmaf(cw3, xi[l], cb);
        if (l >= 1) a = fmaf(cw2, xi[l - 1], a);
        if (l >= 2) a = fmaf(cw1, xi[l - 2], a);
        if (l >= 3) a = fmaf(cw0, xi[l - 3], a);
        a = a * (1.f / (1.f + __expf(-a)));
        xc[l] = a;
        s_xc[warp][l * 33 + lane] = a;
    }
    __syncwarp();

    // distributed dtin: lane handles l = lane>>2, d-part = (lane&3)*8..+7
    float dtpart = 0.f;
    {
        const int lml = lane >> 2;
        const int dp0 = (lane & 3) * 8;
#pragma unroll
        for (int dd = 0; dd < 8; dd++)
            dtpart = fmaf(s_xc[warp][lml * 33 + dp0 + dd],
                          s_xpwt[(dp0 + dd) * 33], dtpart);
        dtpart += __shfl_xor_sync(0xFFFFFFFFu, dtpart, 1);
        dtpart += __shfl_xor_sync(0xFFFFFFFFu, dtpart, 2);
    }
    float dtin[LSEQ];
#pragma unroll
    for (int l = 0; l < LSEQ; l++)
        dtin[l] = __shfl_sync(0xFFFFFFFFu, dtpart, l << 2);

    // B/C projection: lane -> e = 1+lane
#pragma unroll
    for (int l = 0; l < LSEQ; l++) {
        float s1 = 0.f;
#pragma unroll
        for (int d = 0; d < D_INNER; d++)
            s1 = fmaf(s_xc[warp][l * 33 + d], s_xpwt[d * 33 + 1 + lane], s1);
        s_bc[warp][l * 32 + lane] = s1;
    }
    __syncwarp();

    float Areg[D_STATE];
#pragma unroll
    for (int s = 0; s < D_STATE; s++) Areg[s] = s_At[s * 32 + lane];
    float hreg[D_STATE];
#pragma unroll
    for (int s = 0; s < D_STATE; s++) hreg[s] = 0.f;

    const float dtwv = s_dtw[lane], dtbv = s_dtb[lane], Dv = s_D[lane];

#pragma unroll
    for (int l = 0; l < LSEQ; l++) {
        float pre = fmaf(dtin[l], dtwv, dtbv);
        float dt = (pre > 20.f) ? pre : log1pf(__expf(pre));
        float cBx = dt * xc[l];
        float yacc = 0.f;
#pragma unroll
        for (int s = 0; s < D_STATE; s++) {
            float dA = __expf(dt * Areg[s]);
            float Bv = s_bc[warp][l * 32 + s];
            float Cv = s_bc[warp][l * 32 + 16 + s];
            hreg[s] = fmaf(dA, hreg[s], cBx * Bv);
            yacc = fmaf(hreg[s], Cv, yacc);
        }
        float ym = fmaf(Dv, xc[l], yacc);
        float zz = zv[l];
        ym = ym * (zz * (1.f / (1.f + __expf(-zz))));
        s_xc[warp][l * 33 + lane] = ym;
    }
    __syncwarp();

    float ps1 = 0.f, ps2 = 0.f;
    const int g = lane & 15;
    const int lh = lane >> 4;
    float* outp = g_m + (size_t)n * 128;
#pragma unroll
    for (int i = 0; i < 4; i++) {
        int l = i * 2 + lh;
        float a2 = 0.f;
#pragma unroll
        for (int d = 0; d < D_INNER; d++)
            a2 = fmaf(s_xc[warp][l * 33 + d], s_opwt[d * 16 + g], a2);
        outp[l * GCN + g] = a2;
        ps1 += a2;
        ps2 = fmaf(a2, a2, ps2);
    }

#pragma unroll
    for (int off = 16; off; off >>= 1) {
        ps1 += __shfl_xor_sync(0xFFFFFFFFu, ps1, off);
        ps2 += __shfl_xor_sync(0xFFFFFFFFu, ps2, off);
    }
    if (lane == 0) {
        atomicAdd(&sm_s1, ps1);
        atomicAdd(&sm_s2, ps2);
    }
    __syncthreads();
    if (tid == 0) {
        int bg = b * 4 + (c >> 5);
        atomicAdd(&g_stats[bg * 2 + 0], sm_s1);
        atomicAdd(&g_stats[bg * 2 + 1], sm_s2);
    }
}

// ---------------------------------------------------------------------------
// GroupNorm + SiLU + residual
// ---------------------------------------------------------------------------
__global__ __launch_bounds__(256) void apply_kernel(
    const float* __restrict__ x, const float* __restrict__ gnw,
    const float* __restrict__ gnb, float* __restrict__ out)
{
    int idx4 = blockIdx.x * blockDim.x + threadIdx.x;
    if (idx4 >= TOT / 4) return;
    int idx = idx4 * 4;
    int c  = (idx >> 14) & 127;
    int bg = (idx >> 21) * 4 + (c >> 5);
    float s1 = g_stats[bg * 2], s2 = g_stats[bg * 2 + 1];
    const float inv_cnt = 1.f / (float)GRP_CNT;
    float mu  = s1 * inv_cnt;
    float var = fmaf(s2, inv_cnt, -mu * mu);
    float rstd = rsqrtf(var + 1e-5f);
    float gw = gnw[c] * rstd;
    float gb = gnb[c];

    float4 xv = *(const float4*)&x[idx];
    float4 mv = *(const float4*)&g_m[idx];
    float4 o;
    { float t = fmaf(mv.x - mu, gw, gb); o.x = xv.x + t * (1.f / (1.f + __expf(-t))); }
    { float t = fmaf(mv.y - mu, gw, gb); o.y = xv.y + t * (1.f / (1.f + __expf(-t))); }
    { float t = fmaf(mv.z - mu, gw, gb); o.z = xv.z + t * (1.f / (1.f + __expf(-t))); }
    { float t = fmaf(mv.w - mu, gw, gb); o.w = xv.w + t * (1.f / (1.f + __expf(-t))); }
    *(float4*)&out[idx] = o;
}

// ---------------------------------------------------------------------------
// Launch
// ---------------------------------------------------------------------------
extern "C" void kernel_launch(void* const* d_in, const int* in_sizes, int n_in,
                              void* d_out, int out_size)
{
    const float* x          = (const float*)d_in[0];
    const float* conv_w     = (const float*)d_in[1];
    const float* conv_b     = (const float*)d_in[2];
    const float* gn_w       = (const float*)d_in[3];
    const float* gn_b       = (const float*)d_in[4];
    const float* in_proj_w  = (const float*)d_in[5];
    const float* conv1d_w   = (const float*)d_in[6];
    const float* conv1d_b   = (const float*)d_in[7];
    const float* x_proj_w   = (const float*)d_in[8];
    const float* dt_proj_w  = (const float*)d_in[9];
    const float* dt_proj_b  = (const float*)d_in[10];
    const float* A_log      = (const float*)d_in[11];
    const float* Dp         = (const float*)d_in[12];
    const float* out_proj_w = (const float*)d_in[13];
    float* out = (float*)d_out;

    static int smem_set = 0;
    if (!smem_set) {
        cudaFuncSetAttribute(conv_mma_kernel,
                             cudaFuncAttributeMaxDynamicSharedMemorySize, CSMEM);
        smem_set = 1;
    }

    prep_kernel<<<576, 256>>>(conv_w);

    dim3 cgrid(HH, BN);
    conv_mma_kernel<<<cgrid, 256, CSMEM>>>(x, conv_b);

    mamba_kernel<<<NSEQ / 8, 256>>>(in_proj_w, conv1d_w, conv1d_b, x_proj_w,
                                    dt_proj_w, dt_proj_b, A_log, Dp, out_proj_w);

    apply_kernel<<<(TOT / 4 + 255) / 256, 256>>>(x, gn_w, gn_b, out);
}

// round 13
// speedup vs baseline: 1.8565x; 1.8565x over previous
#include <cuda_runtime.h>
#include <cuda_fp16.h>
#include <math.h>
#include <stdint.h>

// ---------------------------------------------------------------------------
// Problem constants
// ---------------------------------------------------------------------------
#define BN   2
#define CH   128
#define HH   128
#define WW   128
#define TOT  (BN*CH*HH*WW)          // 4194304
#define NSEQ (BN*CH*HH)             // 32768 sequences
#define D_INNER 32
#define D_STATE 16
#define GCN  16
#define LSEQ 8
#define GROUPS 4
#define GRP_CNT ((CH/GROUPS)*HH*WW) // 524288 per (b, group)

// ---------------------------------------------------------------------------
// Scratch (static device memory; no allocation allowed)
// ---------------------------------------------------------------------------
__device__ float g_y[TOT];       // conv2d output
__device__ float g_m[TOT];       // mamba output (pre-GroupNorm)
__device__ float g_stats[16];    // (b,group) -> {sum, sumsq}
// weight tiles: [tap 0..8], each 128ci x 128co fp16, swizzled, 32KB
__device__ __align__(16) unsigned char g_wt[9 * 32768];

// smem layout for conv kernel (dynamic):
//  [0,      34816)  A tile: 136 rows(wp) x 128 ci fp16, 256B rows, swizzled
//  [34816, 100352)  2 weight buffers x 32768 (double buffer)
//  bounce (epilogue) reuses [0, 67584): 128 w x 132 co f32
#define AH_OFF 0
#define W_OFF  34816
#define CSMEM  (W_OFF + 2*32768)   // 100352

// swizzle: off = row*256 + col2B; phys = off ^ ((row&7)<<4)
__host__ __device__ __forceinline__ uint32_t swz(uint32_t row, uint32_t colByte) {
    uint32_t off = row * 256u + colByte;
    return off ^ ((row & 7u) << 4);
}

__device__ __forceinline__ uint32_t smem_u32(const void* p) {
    uint32_t a;
    asm("{ .reg .u64 t; cvta.to.shared.u64 t, %1; cvt.u32.u64 %0, t; }" : "=r"(a) : "l"(p));
    return a;
}

#define LDSM_X4(r0,r1,r2,r3,addr) \
    asm volatile("ldmatrix.sync.aligned.m8n8.x4.shared.b16 {%0,%1,%2,%3}, [%4];" \
        : "=r"(r0), "=r"(r1), "=r"(r2), "=r"(r3) : "r"(addr))
#define LDSM_X4_T(r0,r1,r2,r3,addr) \
    asm volatile("ldmatrix.sync.aligned.m8n8.x4.trans.shared.b16 {%0,%1,%2,%3}, [%4];" \
        : "=r"(r0), "=r"(r1), "=r"(r2), "=r"(r3) : "r"(addr))
#define MMA16816(c0,c1,c2,c3,a0,a1,a2,a3,b0,b1) \
    asm volatile("mma.sync.aligned.m16n8k16.row.col.f32.f16.f16.f32 " \
        "{%0,%1,%2,%3}, {%4,%5,%6,%7}, {%8,%9}, {%0,%1,%2,%3};" \
        : "+f"(c0), "+f"(c1), "+f"(c2), "+f"(c3) \
        : "r"(a0), "r"(a1), "r"(a2), "r"(a3), "r"(b0), "r"(b1))
#define CP_ASYNC16(dst, src) \
    asm volatile("cp.async.cg.shared.global [%0], [%1], 16;" :: "r"(dst), "l"(src))
#define CP_COMMIT() asm volatile("cp.async.commit_group;")
#define STS128(addr, v) \
    asm volatile("st.shared.v4.b32 [%0], {%1,%2,%3,%4};" \
        :: "r"(addr), "r"((v).x), "r"((v).y), "r"((v).z), "r"((v).w) : "memory")

// ---------------------------------------------------------------------------
// Prep: conv weights -> fp16 swizzled [ci][co] tiles; zero stats
// ---------------------------------------------------------------------------
__global__ void prep_kernel(const float* __restrict__ cw) {
    int idx = blockIdx.x * 256 + threadIdx.x;
    if (blockIdx.x == 0 && threadIdx.x < 16) g_stats[threadIdx.x] = 0.f;
    if (idx >= 9 * 128 * 128) return;
    int tap = idx >> 14;
    int rem = idx & 16383;
    int ci = rem >> 7, co = rem & 127;
    float v = cw[co * 1152 + ci * 9 + tap];
    uint32_t o = swz((uint32_t)ci, (uint32_t)co * 2u);
    *(__half*)(g_wt + (size_t)tap * 32768 + o) = __float2half(v);
}

// ---------------------------------------------------------------------------
// Conv 3x3 via mma.sync fp16. One block = one (b,h). Conflict-free A build.
// ---------------------------------------------------------------------------
__global__ __launch_bounds__(256, 2) void conv_mma_kernel(
    const float* __restrict__ x, const float* __restrict__ bias)
{
    extern __shared__ __align__(1024) char smem[];
    const uint32_t sb = smem_u32(smem);
    const int tid = threadIdx.x, warp = tid >> 5, lane = tid & 31;
    const int h = blockIdx.x, b = blockIdx.y;
    const int m0 = warp * 16;           // w-row base for this warp (MMA)

    float acc[64];
#pragma unroll
    for (int i = 0; i < 64; i++) acc[i] = 0.f;

    // zero halo rows 0 and 129 (never overwritten by per-dh builds)
    if (tid < 32) {
        uint32_t row = (tid < 16) ? 0u : 129u;
        uint32_t c16 = (uint32_t)(tid & 15);
        uint4 z = make_uint4(0u, 0u, 0u, 0u);
        STS128(sb + AH_OFF + swz(row, c16 * 16u), z);
    }

    // prologue: prefetch weight tile 0 into slot 0
    {
        const char* src = (const char*)g_wt + tid * 16;
        uint32_t dst = sb + W_OFF + tid * 16;
#pragma unroll
        for (int i = 0; i < 8; i++) CP_ASYNC16(dst + i * 4096, src + i * 4096);
        CP_COMMIT();
    }
    int issued = 1;

    // A-build lane geometry: lane <-> w position (coalesced LDG, STS.128)
    const int wp = (warp & 3) * 32 + lane + 1;     // A row 1..128
    const int wg = wp - 1;                         // global w
    const int cihalf = (warp >> 2) * 64;           // ci half per warp group

#pragma unroll 1
    for (int dh = 0; dh < 3; dh++) {
        __syncthreads();   // everyone done reading previous A
        // ---- build A tile (fp16): 8 octets of 8 ci per thread ----
        {
            const int hr = h + dh - 1;
            const bool valid = (hr >= 0) && (hr < HH);
            const float* xrow = x + ((size_t)(b * CH) * HH + hr) * WW + wg;
#pragma unroll
            for (int oct = 0; oct < 8; oct++) {
                const int ci0 = cihalf + oct * 8;
                uint4 pk;
                uint32_t* pku = (uint32_t*)&pk;
#pragma unroll
                for (int j = 0; j < 4; j++) {
                    float f0 = valid ? xrow[(size_t)(ci0 + 2 * j) * (HH * WW)] : 0.f;
                    float f1 = valid ? xrow[(size_t)(ci0 + 2 * j + 1) * (HH * WW)] : 0.f;
                    __half2 h2 = __floats2half2_rn(f0, f1);
                    pku[j] = *reinterpret_cast<uint32_t*>(&h2);
                }
                STS128(sb + AH_OFF + swz((uint32_t)wp, (uint32_t)ci0 * 2u), pk);
            }
        }

#pragma unroll 1
        for (int dw = 0; dw < 3; dw++) {
            const int L = dh * 3 + dw;
            asm volatile("cp.async.wait_group 0;");
            __syncthreads();
            if (issued < 9) {
                const char* src = (const char*)g_wt + (size_t)issued * 32768 + tid * 16;
                uint32_t dst = sb + W_OFF + (uint32_t)(issued & 1) * 32768 + tid * 16;
#pragma unroll
                for (int i = 0; i < 8; i++) CP_ASYNC16(dst + i * 4096, src + i * 4096);
                CP_COMMIT();
                issued++;
            }
            const uint32_t wB = sb + W_OFF + (uint32_t)(L & 1) * 32768;
            const uint32_t arow = (uint32_t)(m0 + dw + ((lane >> 3) & 1) * 8 + (lane & 7));
            const uint32_t arbase = sb + AH_OFF + arow * 256u;
            const uint32_t axor = (arow & 7u) << 4;
            const uint32_t brow = (uint32_t)(lane & 15);
            const uint32_t bg = (uint32_t)(lane >> 4);
#pragma unroll
            for (int ks = 0; ks < 8; ks++) {
                uint32_t a0, a1, a2, a3;
                uint32_t aaddr = arbase + ((((uint32_t)(ks * 2) + bg) << 4) ^ axor);
                LDSM_X4(a0, a1, a2, a3, aaddr);
                const uint32_t br = (uint32_t)(ks * 16) + brow;
                const uint32_t brbase = wB + br * 256u;
                const uint32_t bxor = (br & 7u) << 4;
#pragma unroll
                for (int j2 = 0; j2 < 8; j2++) {
                    uint32_t b0, b1, b2, b3;
                    uint32_t baddr = brbase + ((((uint32_t)(j2 * 2) + bg) << 4) ^ bxor);
                    LDSM_X4_T(b0, b1, b2, b3, baddr);
                    MMA16816(acc[j2 * 8 + 0], acc[j2 * 8 + 1], acc[j2 * 8 + 2], acc[j2 * 8 + 3],
                             a0, a1, a2, a3, b0, b1);
                    MMA16816(acc[j2 * 8 + 4], acc[j2 * 8 + 5], acc[j2 * 8 + 6], acc[j2 * 8 + 7],
                             a0, a1, a2, a3, b2, b3);
                }
            }
        }
    }

    // ---- epilogue: regs -> bounce[w][co] (+bias) -> transposed global ----
    __syncthreads();
    {
        float* bounce = (float*)smem;          // [128][132]
        const int q = lane >> 2, p = lane & 3;
        const int r0 = m0 + q, r1 = m0 + q + 8;
#pragma unroll
        for (int j = 0; j < 16; j++) {
            const int co = j * 8 + p * 2;
            float2 bv = *(const float2*)&bias[co];
            *(float2*)&bounce[r0 * 132 + co] =
                make_float2(acc[j * 4 + 0] + bv.x, acc[j * 4 + 1] + bv.y);
            *(float2*)&bounce[r1 * 132 + co] =
                make_float2(acc[j * 4 + 2] + bv.x, acc[j * 4 + 3] + bv.y);
        }
        __syncthreads();
        const int co2 = tid >> 1, seg = (tid & 1) * 64;
        float* dst = &g_y[((b * CH + co2) * HH + h) * WW + seg];
#pragma unroll
        for (int j = 0; j < 64; j += 4) {
            *(float4*)&dst[j] = make_float4(
                bounce[(seg + j + 0) * 132 + co2], bounce[(seg + j + 1) * 132 + co2],
                bounce[(seg + j + 2) * 132 + co2], bounce[(seg + j + 3) * 132 + co2]);
        }
    }
}

// ---------------------------------------------------------------------------
// Mamba kernel: one warp per sequence, lane = d_inner channel.
// Wide (float4) broadcast LDS everywhere; dtin via shuffle butterfly.
// ---------------------------------------------------------------------------
__global__ __launch_bounds__(256) void mamba_kernel(
    const float* __restrict__ in_proj_w, const float* __restrict__ c1w,
    const float* __restrict__ c1b, const float* __restrict__ xpw,
    const float* __restrict__ dtw, const float* __restrict__ dtb,
    const float* __restrict__ A_log, const float* __restrict__ Dp,
    const float* __restrict__ opw)
{
    __shared__ __align__(16) float s_ipw[16 * 64];    // [k][e]
    __shared__ __align__(16) float s_xpwt[32 * 33];   // [d][e]
    __shared__ __align__(16) float s_At[16 * 32];     // [s][d]
    __shared__ __align__(16) float s_opwt[32 * 16];   // [d][g]
    __shared__ float s_c1w[32 * 4];
    __shared__ float s_c1b[32], s_dtw[32], s_dtb[32], s_D[32];
    __shared__ __align__(16) float s_seq[8][128];
    __shared__ __align__(16) float s_xc[8][LSEQ * 32];
    __shared__ __align__(16) float s_bc[8][LSEQ * 32];
    __shared__ float sm_s1, sm_s2;

    const int tid = threadIdx.x;

    for (int idx = tid; idx < 16 * 64; idx += 256) {
        int k = idx >> 6, e = idx & 63;
        s_ipw[idx] = in_proj_w[e * 16 + k];
    }
    for (int idx = tid; idx < 32 * 33; idx += 256) {
        int d = idx / 33, e = idx - d * 33;
        s_xpwt[idx] = xpw[e * 32 + d];
    }
    for (int idx = tid; idx < 16 * 32; idx += 256) {
        int s = idx >> 5, d = idx & 31;
        s_At[idx] = -__expf(A_log[d * 16 + s]);
    }
    for (int idx = tid; idx < 32 * 16; idx += 256) {
        int d = idx >> 4, g = idx & 15;
        s_opwt[idx] = opw[g * 32 + d];
    }
    if (tid < 128) s_c1w[tid] = c1w[tid];
    if (tid < 32) {
        s_c1b[tid] = c1b[tid];
        s_dtw[tid] = dtw[tid];
        s_dtb[tid] = dtb[tid];
        s_D[tid]   = Dp[tid];
    }
    if (tid == 0) { sm_s1 = 0.f; sm_s2 = 0.f; }
    __syncthreads();

    const int warp = tid >> 5;
    const int lane = tid & 31;
    const int n = blockIdx.x * 8 + warp;
    const int c = (n >> 7) & 127;
    const int b = n >> 14;

    const float* yrow = g_y + (size_t)n * 128;
    float* seq = s_seq[warp];
#pragma unroll
    for (int i = 0; i < 4; i++) seq[i * 32 + lane] = yrow[i * 32 + lane];
    __syncwarp();

    // ---- in_proj (float4 broadcast seq reads, weights in regs) ----
    float wx[16], wz[16];
#pragma unroll
    for (int k = 0; k < 16; k++) {
        wx[k] = s_ipw[k * 64 + lane];
        wz[k] = s_ipw[k * 64 + 32 + lane];
    }
    float xi[LSEQ], zv[LSEQ];
#pragma unroll
    for (int l = 0; l < LSEQ; l++) {
        float sx = 0.f, sz = 0.f;
#pragma unroll
        for (int k4 = 0; k4 < 4; k4++) {
            float4 s4 = *(const float4*)&seq[l * 16 + k4 * 4];
            sx = fmaf(s4.x, wx[k4*4+0], sx); sz = fmaf(s4.x, wz[k4*4+0], sz);
            sx = fmaf(s4.y, wx[k4*4+1], sx); sz = fmaf(s4.y, wz[k4*4+1], sz);
            sx = fmaf(s4.z, wx[k4*4+2], sx); sz = fmaf(s4.z, wz[k4*4+2], sz);
            sx = fmaf(s4.w, wx[k4*4+3], sx); sz = fmaf(s4.w, wz[k4*4+3], sz);
        }
        xi[l] = sx; zv[l] = sz;
    }

    // ---- causal depthwise conv1d + SiLU ----
    float cw0 = s_c1w[lane * 4 + 0], cw1 = s_c1w[lane * 4 + 1];
    float cw2 = s_c1w[lane * 4 + 2], cw3 = s_c1w[lane * 4 + 3];
    float cb = s_c1b[lane];
    float xc[LSEQ];
#pragma unroll
    for (int l = 0; l < LSEQ; l++) {
        float a = fmaf(cw3, xi[l], cb);
        if (l >= 1) a = fmaf(cw2, xi[l - 1], a);
        if (l >= 2) a = fmaf(cw1, xi[l - 2], a);
        if (l >= 3) a = fmaf(cw0, xi[l - 3], a);
        a = a * (1.f / (1.f + __expf(-a)));
        xc[l] = a;
        s_xc[warp][l * 32 + lane] = a;
    }
    __syncwarp();

    // ---- dtin: butterfly reduction per l (xc resident in lane regs) ----
    const float wdt = s_xpwt[lane * 33];     // dt column, d = lane
    float dtin[LSEQ];
#pragma unroll
    for (int l = 0; l < LSEQ; l++) {
        float t = xc[l] * wdt;
        t += __shfl_xor_sync(0xFFFFFFFFu, t, 16);
        t += __shfl_xor_sync(0xFFFFFFFFu, t, 8);
        t += __shfl_xor_sync(0xFFFFFFFFu, t, 4);
        t += __shfl_xor_sync(0xFFFFFFFFu, t, 2);
        t += __shfl_xor_sync(0xFFFFFFFFu, t, 1);
        dtin[l] = t;
    }

    // ---- B/C projection (float4 broadcast xc, weights in regs) ----
    float wbc[32];
#pragma unroll
    for (int d = 0; d < 32; d++) wbc[d] = s_xpwt[d * 33 + 1 + lane];
#pragma unroll
    for (int l = 0; l < LSEQ; l++) {
        float s1 = 0.f;
#pragma unroll
        for (int d4 = 0; d4 < 8; d4++) {
            float4 v = *(const float4*)&s_xc[warp][l * 32 + d4 * 4];
            s1 = fmaf(v.x, wbc[d4*4+0], s1);
            s1 = fmaf(v.y, wbc[d4*4+1], s1);
            s1 = fmaf(v.z, wbc[d4*4+2], s1);
            s1 = fmaf(v.w, wbc[d4*4+3], s1);
        }
        s_bc[warp][l * 32 + lane] = s1;
    }
    __syncwarp();

    // ---- selective scan ----
    float Areg[D_STATE];
#pragma unroll
    for (int s = 0; s < D_STATE; s++) Areg[s] = s_At[s * 32 + lane];
    float hreg[D_STATE];
#pragma unroll
    for (int s = 0; s < D_STATE; s++) hreg[s] = 0.f;

    const float dtwv = s_dtw[lane], dtbv = s_dtb[lane], Dv = s_D[lane];

#pragma unroll
    for (int l = 0; l < LSEQ; l++) {
        float pre = fmaf(dtin[l], dtwv, dtbv);
        float dt = (pre > 20.f) ? pre : log1pf(__expf(pre));
        float cBx = dt * xc[l];
        float Bv[16], Cv[16];
#pragma unroll
        for (int s4 = 0; s4 < 4; s4++) {
            float4 bq = *(const float4*)&s_bc[warp][l * 32 + s4 * 4];
            Bv[s4*4+0]=bq.x; Bv[s4*4+1]=bq.y; Bv[s4*4+2]=bq.z; Bv[s4*4+3]=bq.w;
            float4 cq = *(const float4*)&s_bc[warp][l * 32 + 16 + s4 * 4];
            Cv[s4*4+0]=cq.x; Cv[s4*4+1]=cq.y; Cv[s4*4+2]=cq.z; Cv[s4*4+3]=cq.w;
        }
        float yacc = 0.f;
#pragma unroll
        for (int s = 0; s < D_STATE; s++) {
            float dA = __expf(dt * Areg[s]);
            hreg[s] = fmaf(dA, hreg[s], cBx * Bv[s]);
            yacc = fmaf(hreg[s], Cv[s], yacc);
        }
        float ym = fmaf(Dv, xc[l], yacc);
        float zz = zv[l];
        ym = ym * (zz * (1.f / (1.f + __expf(-zz))));
        s_xc[warp][l * 32 + lane] = ym;     // reuse for ym
    }
    __syncwarp();

    // ---- out_proj (float4 broadcast ym, weights in regs) ----
    float ps1 = 0.f, ps2 = 0.f;
    const int g = lane & 15;
    const int lh = lane >> 4;
    float wop[32];
#pragma unroll
    for (int d = 0; d < 32; d++) wop[d] = s_opwt[d * 16 + g];
    float* outp = g_m + (size_t)n * 128;
#pragma unroll
    for (int i = 0; i < 4; i++) {
        int l = i * 2 + lh;
        float a2 = 0.f;
#pragma unroll
        for (int d4 = 0; d4 < 8; d4++) {
            float4 v = *(const float4*)&s_xc[warp][l * 32 + d4 * 4];
            a2 = fmaf(v.x, wop[d4*4+0], a2);
            a2 = fmaf(v.y, wop[d4*4+1], a2);
            a2 = fmaf(v.z, wop[d4*4+2], a2);
            a2 = fmaf(v.w, wop[d4*4+3], a2);
        }
        outp[l * GCN + g] = a2;
        ps1 += a2;
        ps2 = fmaf(a2, a2, ps2);
    }

#pragma unroll
    for (int off = 16; off; off >>= 1) {
        ps1 += __shfl_xor_sync(0xFFFFFFFFu, ps1, off);
        ps2 += __shfl_xor_sync(0xFFFFFFFFu, ps2, off);
    }
    if (lane == 0) {
        atomicAdd(&sm_s1, ps1);
        atomicAdd(&sm_s2, ps2);
    }
    __syncthreads();
    if (tid == 0) {
        int bg = b * 4 + (c >> 5);
        atomicAdd(&g_stats[bg * 2 + 0], sm_s1);
        atomicAdd(&g_stats[bg * 2 + 1], sm_s2);
    }
}

// ---------------------------------------------------------------------------
// GroupNorm + SiLU + residual
// ---------------------------------------------------------------------------
__global__ __launch_bounds__(256) void apply_kernel(
    const float* __restrict__ x, const float* __restrict__ gnw,
    const float* __restrict__ gnb, float* __restrict__ out)
{
    int idx4 = blockIdx.x * blockDim.x + threadIdx.x;
    if (idx4 >= TOT / 4) return;
    int idx = idx4 * 4;
    int c  = (idx >> 14) & 127;
    int bg = (idx >> 21) * 4 + (c >> 5);
    float s1 = g_stats[bg * 2], s2 = g_stats[bg * 2 + 1];
    const float inv_cnt = 1.f / (float)GRP_CNT;
    float mu  = s1 * inv_cnt;
    float var = fmaf(s2, inv_cnt, -mu * mu);
    float rstd = rsqrtf(var + 1e-5f);
    float gw = gnw[c] * rstd;
    float gb = gnb[c];

    float4 xv = *(const float4*)&x[idx];
    float4 mv = *(const float4*)&g_m[idx];
    float4 o;
    { float t = fmaf(mv.x - mu, gw, gb); o.x = xv.x + t * (1.f / (1.f + __expf(-t))); }
    { float t = fmaf(mv.y - mu, gw, gb); o.y = xv.y + t * (1.f / (1.f + __expf(-t))); }
    { float t = fmaf(mv.z - mu, gw, gb); o.z = xv.z + t * (1.f / (1.f + __expf(-t))); }
    { float t = fmaf(mv.w - mu, gw, gb); o.w = xv.w + t * (1.f / (1.f + __expf(-t))); }
    *(float4*)&out[idx] = o;
}

// ---------------------------------------------------------------------------
// Launch
// ---------------------------------------------------------------------------
extern "C" void kernel_launch(void* const* d_in, const int* in_sizes, int n_in,
                              void* d_out, int out_size)
{
    const float* x          = (const float*)d_in[0];
    const float* conv_w     = (const float*)d_in[1];
    const float* conv_b     = (const float*)d_in[2];
    const float* gn_w       = (const float*)d_in[3];
    const float* gn_b       = (const float*)d_in[4];
    const float* in_proj_w  = (const float*)d_in[5];
    const float* conv1d_w   = (const float*)d_in[6];
    const float* conv1d_b   = (const float*)d_in[7];
    const float* x_proj_w   = (const float*)d_in[8];
    const float* dt_proj_w  = (const float*)d_in[9];
    const float* dt_proj_b  = (const float*)d_in[10];
    const float* A_log      = (const float*)d_in[11];
    const float* Dp         = (const float*)d_in[12];
    const float* out_proj_w = (const float*)d_in[13];
    float* out = (float*)d_out;

    static int smem_set = 0;
    if (!smem_set) {
        cudaFuncSetAttribute(conv_mma_kernel,
                             cudaFuncAttributeMaxDynamicSharedMemorySize, CSMEM);
        smem_set = 1;
    }

    prep_kernel<<<576, 256>>>(conv_w);

    dim3 cgrid(HH, BN);
    conv_mma_kernel<<<cgrid, 256, CSMEM>>>(x, conv_b);

    mamba_kernel<<<NSEQ / 8, 256>>>(in_proj_w, conv1d_w, conv1d_b, x_proj_w,
                                    dt_proj_w, dt_proj_b, A_log, Dp, out_proj_w);

    apply_kernel<<<(TOT / 4 + 255) / 256, 256>>>(x, gn_w, gn_b, out);
}

// round 14
// speedup vs baseline: 2.3116x; 1.2451x over previous
#include <cuda_runtime.h>
#include <cuda_fp16.h>
#include <math.h>
#include <stdint.h>

// ---------------------------------------------------------------------------
// Problem constants
// ---------------------------------------------------------------------------
#define BN   2
#define CH   128
#define HH   128
#define WW   128
#define TOT  (BN*CH*HH*WW)          // 4194304
#define NSEQ (BN*CH*HH)             // 32768 sequences
#define D_INNER 32
#define D_STATE 16
#define GCN  16
#define LSEQ 8
#define GROUPS 4
#define GRP_CNT ((CH/GROUPS)*HH*WW) // 524288 per (b, group)
#define LOG2E 1.4426950408889634f
#define LN2   0.6931471805599453f

typedef unsigned long long u64;

// fast-math asm (base PTX, safe for compute_103)
#define EX2(d,a)  asm("ex2.approx.f32 %0, %1;" : "=f"(d) : "f"(a))
#define LG2(d,a)  asm("lg2.approx.f32 %0, %1;" : "=f"(d) : "f"(a))
#define RCPA(d,a) asm("rcp.approx.f32 %0, %1;" : "=f"(d) : "f"(a))
// packed fp32x2 ops
#define FMA2(d,a,b,c) asm("fma.rn.f32x2 %0, %1, %2, %3;" : "=l"(d) : "l"(a), "l"(b), "l"(c))
#define MUL2(d,a,b)   asm("mul.rn.f32x2 %0, %1, %2;" : "=l"(d) : "l"(a), "l"(b))
#define PK2(d,lo,hi)  asm("mov.b64 %0, {%1, %2};" : "=l"(d) : "r"(__float_as_uint(lo)), "r"(__float_as_uint(hi)))
#define UPK2(lo,hi,s) asm("mov.b64 {%0, %1}, %2;" : "=r"(lo), "=r"(hi) : "l"(s))

__device__ __forceinline__ float silu_f(float a) {
    float e, r;
    EX2(e, -a * LOG2E);
    RCPA(r, 1.f + e);
    return a * r;
}

// ---------------------------------------------------------------------------
// Scratch (static device memory; no allocation allowed)
// ---------------------------------------------------------------------------
__device__ float g_y[TOT];       // conv2d output
__device__ float g_m[TOT];       // mamba output (pre-GroupNorm)
__device__ float g_stats[16];    // (b,group) -> {sum, sumsq}
__device__ __align__(16) unsigned char g_wt[9 * 32768];  // conv weight tiles
__device__ __align__(16) float g_mw[3360];               // mamba weight blob

// blob offsets (floats)
#define MW_IPW  0      // [k][e] 16x64
#define MW_XPWT 1024   // [d][e] 32x33
#define MW_AT   2080   // [s][d] 16x32 : -exp(A_log)*log2e
#define MW_OPWT 2592   // [d][g] 32x16
#define MW_C1W  3104   // 128
#define MW_C1B  3232
#define MW_DTW  3264
#define MW_DTB  3296
#define MW_D    3328
#define MW_TOT  3360

// smem layout for conv kernel (dynamic)
#define AH_OFF 0
#define W_OFF  34816
#define CSMEM  (W_OFF + 2*32768)   // 100352

__host__ __device__ __forceinline__ uint32_t swz(uint32_t row, uint32_t colByte) {
    uint32_t off = row * 256u + colByte;
    return off ^ ((row & 7u) << 4);
}

__device__ __forceinline__ uint32_t smem_u32(const void* p) {
    uint32_t a;
    asm("{ .reg .u64 t; cvta.to.shared.u64 t, %1; cvt.u32.u64 %0, t; }" : "=r"(a) : "l"(p));
    return a;
}

#define LDSM_X4(r0,r1,r2,r3,addr) \
    asm volatile("ldmatrix.sync.aligned.m8n8.x4.shared.b16 {%0,%1,%2,%3}, [%4];" \
        : "=r"(r0), "=r"(r1), "=r"(r2), "=r"(r3) : "r"(addr))
#define LDSM_X4_T(r0,r1,r2,r3,addr) \
    asm volatile("ldmatrix.sync.aligned.m8n8.x4.trans.shared.b16 {%0,%1,%2,%3}, [%4];" \
        : "=r"(r0), "=r"(r1), "=r"(r2), "=r"(r3) : "r"(addr))
#define MMA16816(c0,c1,c2,c3,a0,a1,a2,a3,b0,b1) \
    asm volatile("mma.sync.aligned.m16n8k16.row.col.f32.f16.f16.f32 " \
        "{%0,%1,%2,%3}, {%4,%5,%6,%7}, {%8,%9}, {%0,%1,%2,%3};" \
        : "+f"(c0), "+f"(c1), "+f"(c2), "+f"(c3) \
        : "r"(a0), "r"(a1), "r"(a2), "r"(a3), "r"(b0), "r"(b1))
#define CP_ASYNC16(dst, src) \
    asm volatile("cp.async.cg.shared.global [%0], [%1], 16;" :: "r"(dst), "l"(src))
#define CP_COMMIT() asm volatile("cp.async.commit_group;")
#define STS128(addr, v) \
    asm volatile("st.shared.v4.b32 [%0], {%1,%2,%3,%4};" \
        :: "r"(addr), "r"((v).x), "r"((v).y), "r"((v).z), "r"((v).w) : "memory")

// ---------------------------------------------------------------------------
// Prep: conv weights -> fp16 swizzled tiles; mamba weights -> transposed blob
// ---------------------------------------------------------------------------
__global__ void prep_kernel(
    const float* __restrict__ cw,
    const float* __restrict__ in_proj_w, const float* __restrict__ c1w,
    const float* __restrict__ c1b, const float* __restrict__ xpw,
    const float* __restrict__ dtw, const float* __restrict__ dtb,
    const float* __restrict__ A_log, const float* __restrict__ Dp,
    const float* __restrict__ opw)
{
    int gidx = blockIdx.x * 256 + threadIdx.x;
    if (gidx < 16) g_stats[gidx] = 0.f;
    if (gidx < 9 * 128 * 128) {
        int tap = gidx >> 14;
        int rem = gidx & 16383;
        int ci = rem >> 7, co = rem & 127;
        float v = cw[co * 1152 + ci * 9 + tap];
        uint32_t o = swz((uint32_t)ci, (uint32_t)co * 2u);
        *(__half*)(g_wt + (size_t)tap * 32768 + o) = __float2half(v);
        return;
    }
    int t = gidx - 9 * 128 * 128;
    if (t >= MW_TOT) return;
    float v;
    if (t < MW_XPWT) {                       // ipw [k][e]
        int k = t >> 6, e = t & 63;
        v = in_proj_w[e * 16 + k];
    } else if (t < MW_AT) {                  // xpwt [d][e]
        int u = t - MW_XPWT;
        int d = u / 33, e = u - d * 33;
        v = xpw[e * 32 + d];
    } else if (t < MW_OPWT) {                // At [s][d]
        int u = t - MW_AT;
        int s = u >> 5, d = u & 31;
        v = -expf(A_log[d * 16 + s]) * LOG2E;
    } else if (t < MW_C1W) {                 // opwt [d][g]
        int u = t - MW_OPWT;
        int d = u >> 4, g = u & 15;
        v = opw[g * 32 + d];
    } else if (t < MW_C1B) v = c1w[t - MW_C1W];
    else if (t < MW_DTW)  v = c1b[t - MW_C1B];
    else if (t < MW_DTB)  v = dtw[t - MW_DTW];
    else if (t < MW_D)    v = dtb[t - MW_DTB];
    else                  v = Dp[t - MW_D];
    g_mw[t] = v;
}

// ---------------------------------------------------------------------------
// Conv 3x3 via mma.sync fp16 (validated R13 version)
// ---------------------------------------------------------------------------
__global__ __launch_bounds__(256, 2) void conv_mma_kernel(
    const float* __restrict__ x, const float* __restrict__ bias)
{
    extern __shared__ __align__(1024) char smem[];
    const uint32_t sb = smem_u32(smem);
    const int tid = threadIdx.x, warp = tid >> 5, lane = tid & 31;
    const int h = blockIdx.x, b = blockIdx.y;
    const int m0 = warp * 16;

    float acc[64];
#pragma unroll
    for (int i = 0; i < 64; i++) acc[i] = 0.f;

    if (tid < 32) {
        uint32_t row = (tid < 16) ? 0u : 129u;
        uint32_t c16 = (uint32_t)(tid & 15);
        uint4 z = make_uint4(0u, 0u, 0u, 0u);
        STS128(sb + AH_OFF + swz(row, c16 * 16u), z);
    }
    {
        const char* src = (const char*)g_wt + tid * 16;
        uint32_t dst = sb + W_OFF + tid * 16;
#pragma unroll
        for (int i = 0; i < 8; i++) CP_ASYNC16(dst + i * 4096, src + i * 4096);
        CP_COMMIT();
    }
    int issued = 1;

    const int wp = (warp & 3) * 32 + lane + 1;
    const int wg = wp - 1;
    const int cihalf = (warp >> 2) * 64;

#pragma unroll 1
    for (int dh = 0; dh < 3; dh++) {
        __syncthreads();
        {
            const int hr = h + dh - 1;
            const bool valid = (hr >= 0) && (hr < HH);
            const float* xrow = x + ((size_t)(b * CH) * HH + hr) * WW + wg;
#pragma unroll
            for (int oct = 0; oct < 8; oct++) {
                const int ci0 = cihalf + oct * 8;
                uint4 pk;
                uint32_t* pku = (uint32_t*)&pk;
#pragma unroll
                for (int j = 0; j < 4; j++) {
                    float f0 = valid ? xrow[(size_t)(ci0 + 2 * j) * (HH * WW)] : 0.f;
                    float f1 = valid ? xrow[(size_t)(ci0 + 2 * j + 1) * (HH * WW)] : 0.f;
                    __half2 h2 = __floats2half2_rn(f0, f1);
                    pku[j] = *reinterpret_cast<uint32_t*>(&h2);
                }
                STS128(sb + AH_OFF + swz((uint32_t)wp, (uint32_t)ci0 * 2u), pk);
            }
        }
#pragma unroll 1
        for (int dw = 0; dw < 3; dw++) {
            const int L = dh * 3 + dw;
            asm volatile("cp.async.wait_group 0;");
            __syncthreads();
            if (issued < 9) {
                const char* src = (const char*)g_wt + (size_t)issued * 32768 + tid * 16;
                uint32_t dst = sb + W_OFF + (uint32_t)(issued & 1) * 32768 + tid * 16;
#pragma unroll
                for (int i = 0; i < 8; i++) CP_ASYNC16(dst + i * 4096, src + i * 4096);
                CP_COMMIT();
                issued++;
            }
            const uint32_t wB = sb + W_OFF + (uint32_t)(L & 1) * 32768;
            const uint32_t arow = (uint32_t)(m0 + dw + ((lane >> 3) & 1) * 8 + (lane & 7));
            const uint32_t arbase = sb + AH_OFF + arow * 256u;
            const uint32_t axor = (arow & 7u) << 4;
            const uint32_t brow = (uint32_t)(lane & 15);
            const uint32_t bg = (uint32_t)(lane >> 4);
#pragma unroll
            for (int ks = 0; ks < 8; ks++) {
                uint32_t a0, a1, a2, a3;
                uint32_t aaddr = arbase + ((((uint32_t)(ks * 2) + bg) << 4) ^ axor);
                LDSM_X4(a0, a1, a2, a3, aaddr);
                const uint32_t br = (uint32_t)(ks * 16) + brow;
                const uint32_t brbase = wB + br * 256u;
                const uint32_t bxor = (br & 7u) << 4;
#pragma unroll
                for (int j2 = 0; j2 < 8; j2++) {
                    uint32_t b0, b1, b2, b3;
                    uint32_t baddr = brbase + ((((uint32_t)(j2 * 2) + bg) << 4) ^ bxor);
                    LDSM_X4_T(b0, b1, b2, b3, baddr);
                    MMA16816(acc[j2 * 8 + 0], acc[j2 * 8 + 1], acc[j2 * 8 + 2], acc[j2 * 8 + 3],
                             a0, a1, a2, a3, b0, b1);
                    MMA16816(acc[j2 * 8 + 4], acc[j2 * 8 + 5], acc[j2 * 8 + 6], acc[j2 * 8 + 7],
                             a0, a1, a2, a3, b2, b3);
                }
            }
        }
    }
    __syncthreads();
    {
        float* bounce = (float*)smem;
        const int q = lane >> 2, p = lane & 3;
        const int r0 = m0 + q, r1 = m0 + q + 8;
#pragma unroll
        for (int j = 0; j < 16; j++) {
            const int co = j * 8 + p * 2;
            float2 bv = *(const float2*)&bias[co];
            *(float2*)&bounce[r0 * 132 + co] =
                make_float2(acc[j * 4 + 0] + bv.x, acc[j * 4 + 1] + bv.y);
            *(float2*)&bounce[r1 * 132 + co] =
                make_float2(acc[j * 4 + 2] + bv.x, acc[j * 4 + 3] + bv.y);
        }
        __syncthreads();
        const int co2 = tid >> 1, seg = (tid & 1) * 64;
        float* dst = &g_y[((b * CH + co2) * HH + h) * WW + seg];
#pragma unroll
        for (int j = 0; j < 64; j += 4) {
            *(float4*)&dst[j] = make_float4(
                bounce[(seg + j + 0) * 132 + co2], bounce[(seg + j + 1) * 132 + co2],
                bounce[(seg + j + 2) * 132 + co2], bounce[(seg + j + 3) * 132 + co2]);
        }
    }
}

// ---------------------------------------------------------------------------
// Mamba kernel v2: f32x2-packed projections, fast-math MUFU, blob weights.
// One warp per sequence (lane = d_inner). 8 warps / block.
// ---------------------------------------------------------------------------
__global__ __launch_bounds__(256) void mamba_kernel()
{
    __shared__ __align__(16) float s_w[MW_TOT];
    __shared__ __align__(16) float s_seqT[8][192];   // [k*12 + l]
    __shared__ __align__(16) float s_xcT[8][384];    // [d*12 + l]; reused for ym rows
    __shared__ __align__(16) float s_bc[8][256];     // [l*32 + e]
    __shared__ float sm_s1, sm_s2;

    const int tid = threadIdx.x;
    for (int i = tid; i < MW_TOT / 4; i += 256)
        ((float4*)s_w)[i] = ((const float4*)g_mw)[i];
    if (tid == 0) { sm_s1 = 0.f; sm_s2 = 0.f; }
    __syncthreads();

    const float* s_ipw  = s_w + MW_IPW;
    const float* s_xpwt = s_w + MW_XPWT;
    const float* s_At   = s_w + MW_AT;
    const float* s_opwt = s_w + MW_OPWT;
    const float* s_c1w  = s_w + MW_C1W;
    const float* s_c1b  = s_w + MW_C1B;
    const float* s_dtw  = s_w + MW_DTW;
    const float* s_dtb  = s_w + MW_DTB;
    const float* s_D    = s_w + MW_D;

    const int warp = tid >> 5;
    const int lane = tid & 31;
    const int n = blockIdx.x * 8 + warp;
    const int c = (n >> 7) & 127;
    const int b = n >> 14;

    // load sequence transposed: seqT[k][l]
    {
        const float* yrow = g_y + (size_t)n * 128;
#pragma unroll
        for (int i = 0; i < 4; i++) {
            float v = yrow[i * 32 + lane];
            int e0 = i * 32 + lane;
            s_seqT[warp][(e0 & 15) * 12 + (e0 >> 4)] = v;
        }
    }
    __syncwarp();

    // ---- in_proj: packed l-pairs ----
    float wx[16], wz[16];
#pragma unroll
    for (int k = 0; k < 16; k++) {
        wx[k] = s_ipw[k * 64 + lane];
        wz[k] = s_ipw[k * 64 + 32 + lane];
    }
    u64 axi[4], azv[4];
#pragma unroll
    for (int i = 0; i < 4; i++) { axi[i] = 0ull; azv[i] = 0ull; }
#pragma unroll
    for (int k = 0; k < 16; k++) {
        float4 qa = *(const float4*)&s_seqT[warp][k * 12];
        float4 qb = *(const float4*)&s_seqT[warp][k * 12 + 4];
        u64 p01, p23, p45, p67, wx2, wz2;
        PK2(p01, qa.x, qa.y); PK2(p23, qa.z, qa.w);
        PK2(p45, qb.x, qb.y); PK2(p67, qb.z, qb.w);
        PK2(wx2, wx[k], wx[k]); PK2(wz2, wz[k], wz[k]);
        FMA2(axi[0], wx2, p01, axi[0]); FMA2(azv[0], wz2, p01, azv[0]);
        FMA2(axi[1], wx2, p23, axi[1]); FMA2(azv[1], wz2, p23, azv[1]);
        FMA2(axi[2], wx2, p45, axi[2]); FMA2(azv[2], wz2, p45, azv[2]);
        FMA2(axi[3], wx2, p67, axi[3]); FMA2(azv[3], wz2, p67, azv[3]);
    }
    float xi[LSEQ], zv[LSEQ];
#pragma unroll
    for (int i = 0; i < 4; i++) {
        uint32_t lo, hi;
        UPK2(lo, hi, axi[i]);
        xi[2 * i] = __uint_as_float(lo); xi[2 * i + 1] = __uint_as_float(hi);
        UPK2(lo, hi, azv[i]);
        zv[2 * i] = __uint_as_float(lo); zv[2 * i + 1] = __uint_as_float(hi);
    }

    // ---- conv1d + SiLU; write xcT ----
    float cw0 = s_c1w[lane * 4 + 0], cw1 = s_c1w[lane * 4 + 1];
    float cw2 = s_c1w[lane * 4 + 2], cw3 = s_c1w[lane * 4 + 3];
    float cb = s_c1b[lane];
    float xc[LSEQ];
#pragma unroll
    for (int l = 0; l < LSEQ; l++) {
        float a = fmaf(cw3, xi[l], cb);
        if (l >= 1) a = fmaf(cw2, xi[l - 1], a);
        if (l >= 2) a = fmaf(cw1, xi[l - 2], a);
        if (l >= 3) a = fmaf(cw0, xi[l - 3], a);
        xc[l] = silu_f(a);
    }
#pragma unroll
    for (int i = 0; i < 4; i++) {
        asm volatile("st.shared.v2.b32 [%0], {%1,%2};"
            :: "r"(smem_u32(&s_xcT[warp][lane * 12 + 2 * i])),
               "r"(__float_as_uint(xc[2 * i])), "r"(__float_as_uint(xc[2 * i + 1]))
            : "memory");
    }
    __syncwarp();

    // ---- dtin: butterfly over d (xc in regs) ----
    const float wdt = s_xpwt[lane * 33];
    float dtin[LSEQ];
#pragma unroll
    for (int l = 0; l < LSEQ; l++) {
        float t = xc[l] * wdt;
        t += __shfl_xor_sync(0xFFFFFFFFu, t, 16);
        t += __shfl_xor_sync(0xFFFFFFFFu, t, 8);
        t += __shfl_xor_sync(0xFFFFFFFFu, t, 4);
        t += __shfl_xor_sync(0xFFFFFFFFu, t, 2);
        t += __shfl_xor_sync(0xFFFFFFFFu, t, 1);
        dtin[l] = t;
    }

    // ---- B/C projection: packed l-pairs ----
    float wbc[32];
#pragma unroll
    for (int d = 0; d < 32; d++) wbc[d] = s_xpwt[d * 33 + 1 + lane];
    u64 abc[4];
#pragma unroll
    for (int i = 0; i < 4; i++) abc[i] = 0ull;
#pragma unroll
    for (int d = 0; d < 32; d++) {
        float4 qa = *(const float4*)&s_xcT[warp][d * 12];
        float4 qb = *(const float4*)&s_xcT[warp][d * 12 + 4];
        u64 p01, p23, p45, p67, w2;
        PK2(p01, qa.x, qa.y); PK2(p23, qa.z, qa.w);
        PK2(p45, qb.x, qb.y); PK2(p67, qb.z, qb.w);
        PK2(w2, wbc[d], wbc[d]);
        FMA2(abc[0], w2, p01, abc[0]);
        FMA2(abc[1], w2, p23, abc[1]);
        FMA2(abc[2], w2, p45, abc[2]);
        FMA2(abc[3], w2, p67, abc[3]);
    }
#pragma unroll
    for (int i = 0; i < 4; i++) {
        uint32_t lo, hi;
        UPK2(lo, hi, abc[i]);
        s_bc[warp][(2 * i) * 32 + lane] = __uint_as_float(lo);
        s_bc[warp][(2 * i + 1) * 32 + lane] = __uint_as_float(hi);
    }
    __syncwarp();

    // ---- selective scan: packed s-pairs ----
    u64 A2[8], h2[8];
#pragma unroll
    for (int s2 = 0; s2 < 8; s2++) {
        float a0 = s_At[(2 * s2) * 32 + lane];
        float a1 = s_At[(2 * s2 + 1) * 32 + lane];
        PK2(A2[s2], a0, a1);
        h2[s2] = 0ull;
    }
    const float dtwv = s_dtw[lane], dtbv = s_dtb[lane], Dv = s_D[lane];

#pragma unroll
    for (int l = 0; l < LSEQ; l++) {
        float pre = fmaf(dtin[l], dtwv, dtbv);
        float e;  EX2(e, pre * LOG2E);
        float lg; LG2(lg, 1.f + e);
        float dt = (pre > 20.f) ? pre : lg * LN2;
        float cBx = dt * xc[l];
        u64 dt2, cB2;
        PK2(dt2, dt, dt);
        PK2(cB2, cBx, cBx);
        float4 bq0 = *(const float4*)&s_bc[warp][l * 32 + 0];
        float4 bq1 = *(const float4*)&s_bc[warp][l * 32 + 4];
        float4 bq2 = *(const float4*)&s_bc[warp][l * 32 + 8];
        float4 bq3 = *(const float4*)&s_bc[warp][l * 32 + 12];
        float4 cq0 = *(const float4*)&s_bc[warp][l * 32 + 16];
        float4 cq1 = *(const float4*)&s_bc[warp][l * 32 + 20];
        float4 cq2 = *(const float4*)&s_bc[warp][l * 32 + 24];
        float4 cq3 = *(const float4*)&s_bc[warp][l * 32 + 28];
        u64 B2[8], C2[8];
        PK2(B2[0], bq0.x, bq0.y); PK2(B2[1], bq0.z, bq0.w);
        PK2(B2[2], bq1.x, bq1.y); PK2(B2[3], bq1.z, bq1.w);
        PK2(B2[4], bq2.x, bq2.y); PK2(B2[5], bq2.z, bq2.w);
        PK2(B2[6], bq3.x, bq3.y); PK2(B2[7], bq3.z, bq3.w);
        PK2(C2[0], cq0.x, cq0.y); PK2(C2[1], cq0.z, cq0.w);
        PK2(C2[2], cq1.x, cq1.y); PK2(C2[3], cq1.z, cq1.w);
        PK2(C2[4], cq2.x, cq2.y); PK2(C2[5], cq2.z, cq2.w);
        PK2(C2[6], cq3.x, cq3.y); PK2(C2[7], cq3.z, cq3.w);
        u64 y2 = 0ull;
#pragma unroll
        for (int s2 = 0; s2 < 8; s2++) {
            u64 t2, bb2, dA2;
            MUL2(t2, dt2, A2[s2]);          // dt * (A*log2e) pairs
            uint32_t tlo, thi;
            UPK2(tlo, thi, t2);
            float d0, d1;
            EX2(d0, __uint_as_float(tlo));
            EX2(d1, __uint_as_float(thi));
            PK2(dA2, d0, d1);
            MUL2(bb2, cB2, B2[s2]);
            FMA2(h2[s2], dA2, h2[s2], bb2);
            FMA2(y2, h2[s2], C2[s2], y2);
        }
        uint32_t ylo, yhi;
        UPK2(ylo, yhi, y2);
        float yacc = __uint_as_float(ylo) + __uint_as_float(yhi);
        float ym = fmaf(Dv, xc[l], yacc);
        ym = ym * silu_f(zv[l]);
        s_xcT[warp][l * 32 + lane] = ym;    // reuse xcT as row-major ym
    }
    __syncwarp();

    // ---- out_proj ----
    float ps1 = 0.f, ps2 = 0.f;
    const int g = lane & 15;
    const int lh = lane >> 4;
    float wop[32];
#pragma unroll
    for (int d = 0; d < 32; d++) wop[d] = s_opwt[d * 16 + g];
    float* outp = g_m + (size_t)n * 128;
#pragma unroll
    for (int i = 0; i < 4; i++) {
        int l = i * 2 + lh;
        float a2 = 0.f;
#pragma unroll
        for (int d4 = 0; d4 < 8; d4++) {
            float4 v = *(const float4*)&s_xcT[warp][l * 32 + d4 * 4];
            a2 = fmaf(v.x, wop[d4 * 4 + 0], a2);
            a2 = fmaf(v.y, wop[d4 * 4 + 1], a2);
            a2 = fmaf(v.z, wop[d4 * 4 + 2], a2);
            a2 = fmaf(v.w, wop[d4 * 4 + 3], a2);
        }
        outp[l * GCN + g] = a2;
        ps1 += a2;
        ps2 = fmaf(a2, a2, ps2);
    }

#pragma unroll
    for (int off = 16; off; off >>= 1) {
        ps1 += __shfl_xor_sync(0xFFFFFFFFu, ps1, off);
        ps2 += __shfl_xor_sync(0xFFFFFFFFu, ps2, off);
    }
    if (lane == 0) {
        atomicAdd(&sm_s1, ps1);
        atomicAdd(&sm_s2, ps2);
    }
    __syncthreads();
    if (tid == 0) {
        int bg = b * 4 + (c >> 5);
        atomicAdd(&g_stats[bg * 2 + 0], sm_s1);
        atomicAdd(&g_stats[bg * 2 + 1], sm_s2);
    }
}

// ---------------------------------------------------------------------------
// GroupNorm + SiLU + residual
// ---------------------------------------------------------------------------
__global__ __launch_bounds__(256) void apply_kernel(
    const float* __restrict__ x, const float* __restrict__ gnw,
    const float* __restrict__ gnb, float* __restrict__ out)
{
    int idx4 = blockIdx.x * blockDim.x + threadIdx.x;
    if (idx4 >= TOT / 4) return;
    int idx = idx4 * 4;
    int c  = (idx >> 14) & 127;
    int bg = (idx >> 21) * 4 + (c >> 5);
    float s1 = g_stats[bg * 2], s2 = g_stats[bg * 2 + 1];
    const float inv_cnt = 1.f / (float)GRP_CNT;
    float mu  = s1 * inv_cnt;
    float var = fmaf(s2, inv_cnt, -mu * mu);
    float rstd = rsqrtf(var + 1e-5f);
    float gw = gnw[c] * rstd;
    float gb = gnb[c];

    float4 xv = *(const float4*)&x[idx];
    float4 mv = *(const float4*)&g_m[idx];
    float4 o;
    { float t = fmaf(mv.x - mu, gw, gb); o.x = xv.x + silu_f(t); }
    { float t = fmaf(mv.y - mu, gw, gb); o.y = xv.y + silu_f(t); }
    { float t = fmaf(mv.z - mu, gw, gb); o.z = xv.z + silu_f(t); }
    { float t = fmaf(mv.w - mu, gw, gb); o.w = xv.w + silu_f(t); }
    *(float4*)&out[idx] = o;
}

// ---------------------------------------------------------------------------
// Launch
// ---------------------------------------------------------------------------
extern "C" void kernel_launch(void* const* d_in, const int* in_sizes, int n_in,
                              void* d_out, int out_size)
{
    const float* x          = (const float*)d_in[0];
    const float* conv_w     = (const float*)d_in[1];
    const float* conv_b     = (const float*)d_in[2];
    const float* gn_w       = (const float*)d_in[3];
    const float* gn_b       = (const float*)d_in[4];
    const float* in_proj_w  = (const float*)d_in[5];
    const float* conv1d_w   = (const float*)d_in[6];
    const float* conv1d_b   = (const float*)d_in[7];
    const float* x_proj_w   = (const float*)d_in[8];
    const float* dt_proj_w  = (const float*)d_in[9];
    const float* dt_proj_b  = (const float*)d_in[10];
    const float* A_log      = (const float*)d_in[11];
    const float* Dp         = (const float*)d_in[12];
    const float* out_proj_w = (const float*)d_in[13];
    float* out = (float*)d_out;

    static int smem_set = 0;
    if (!smem_set) {
        cudaFuncSetAttribute(conv_mma_kernel,
                             cudaFuncAttributeMaxDynamicSharedMemorySize, CSMEM);
        smem_set = 1;
    }

    // 576 blocks for conv weights + 14 for the mamba blob
    prep_kernel<<<590, 256>>>(conv_w, in_proj_w, conv1d_w, conv1d_b, x_proj_w,
                              dt_proj_w, dt_proj_b, A_log, Dp, out_proj_w);

    dim3 cgrid(HH, BN);
    conv_mma_kernel<<<cgrid, 256, CSMEM>>>(x, conv_b);

    mamba_kernel<<<NSEQ / 8, 256>>>();

    apply_kernel<<<(TOT / 4 + 255) / 256, 256>>>(x, gn_w, gn_b, out);
}